// round 6
// baseline (speedup 1.0000x reference)
#include <cuda_runtime.h>
#include <cuda_bf16.h>
#include <math.h>

#define EPSV 1e-5f

// ---------------- scratch (__device__ globals; zero-init borders load-bearing) --
// conv inputs are CHANNEL-LAST padded: [img][y 34][x 34][C]
__device__ __nv_bfloat16 g_xph[12*34*34*448];
__device__ __nv_bfloat16 g_xpl[12*34*34*448];
__device__ __nv_bfloat16 g_w1h[9*128*448];
__device__ __nv_bfloat16 g_w1l[9*128*448];
__device__ __nv_bfloat16 g_w2h[9*448*128];
__device__ __nv_bfloat16 g_w2l[9*448*128];
__device__ __nv_bfloat16 g_wqh[256*384];
__device__ __nv_bfloat16 g_wql[256*384];
__device__ __nv_bfloat16 g_woh[128*128];
__device__ __nv_bfloat16 g_wol[128*128];
__device__ float         g_conv1[12*128*1024];
__device__ __nv_bfloat16 g_xnh[12*128*1024];
__device__ __nv_bfloat16 g_xnl[12*128*1024];
__device__ float         g_q[4096*256];
__device__ __nv_bfloat16 g_oah[4*1024*128];    // attn out transposed [b][hw][C]
__device__ __nv_bfloat16 g_oal[4*1024*128];
__device__ __nv_bfloat16 g_o2h[4*34*34*128];   // padded conv2 input, channel-last
__device__ __nv_bfloat16 g_o2l[4*34*34*128];
__device__ float         g_u[4*7*65536];
__device__ float g_cmod[64];
__device__ float g_psum[128], g_psq[128], g_stats[8];

// ---------------- helpers ----------------
__device__ __forceinline__ void split2(float v, __nv_bfloat16* h, __nv_bfloat16* l) {
    __nv_bfloat16 hh = __float2bfloat16(v);
    *h = hh;
    *l = __float2bfloat16(v - __bfloat162float(hh));
}
__device__ __forceinline__ float geluf(float v) {
    return 0.5f * v * (1.0f + erff(v * 0.70710678118654752f));
}
__device__ __forceinline__ unsigned ldb2(const __nv_bfloat16* p) {
    return *reinterpret_cast<const unsigned*>(p);
}
__device__ __forceinline__ void mma16816(float* c, unsigned a0, unsigned a1, unsigned a2, unsigned a3,
                                         unsigned b0, unsigned b1) {
    asm volatile("mma.sync.aligned.m16n8k16.row.col.f32.bf16.bf16.f32 "
        "{%0,%1,%2,%3}, {%4,%5,%6,%7}, {%8,%9}, {%0,%1,%2,%3};\n"
        : "+f"(c[0]), "+f"(c[1]), "+f"(c[2]), "+f"(c[3])
        : "r"(a0), "r"(a1), "r"(a2), "r"(a3), "r"(b0), "r"(b1));
}
__device__ __forceinline__ void cpasync16(void* dst_smem, const void* src) {
    unsigned sa = (unsigned)__cvta_generic_to_shared(dst_smem);
    asm volatile("cp.async.cg.shared.global [%0], [%1], 16;\n" :: "r"(sa), "l"(src));
}

// ---------------- 1) pack x -> channel-last padded bf16 hi/lo -------------------
// grid (32 y, 12 img), 256 thr. Two passes over p1-halves (smem 28KB).
__global__ void k_pack(const float* __restrict__ x) {
    __shared__ float s[28 * 256];
    int y = blockIdx.x, nimg = blockIdx.y;   // img = n*7-ish: nimg in [0,12): n*3+s image? NO:
    // images are (b, s): img index = b*3 + s, and x is [b][s][e][256][256] flat -> (img)*7 + e planes
    int tid = threadIdx.x;
#pragma unroll
    for (int half = 0; half < 2; half++) {
        __syncthreads();
        for (int i = tid; i < 28 * 64; i += 256) {
            int row = i >> 6, col4 = i & 63;         // row = e*4 + pp
            int e = row >> 2, pp = row & 3;
            int p1 = half * 4 + pp;
            const float4* src = reinterpret_cast<const float4*>(
                x + (((size_t)nimg * 7 + e) * 256 + y * 8 + p1) * 256) + col4;
            reinterpret_cast<float4*>(s)[row * 64 + col4] = *src;
        }
        __syncthreads();
        for (int i = tid; i < 32 * 224; i += 256) {
            int xq = i / 224, cl = i % 224;
            int p1l = cl / 56, rem = cl % 56, p2 = rem / 7, e = rem % 7;
            float v = s[(e * 4 + p1l) * 256 + xq * 8 + p2];
            int c = half * 224 + cl;
            size_t d = (((size_t)nimg * 34 + y + 1) * 34 + xq + 1) * 448 + c;
            split2(v, &g_xph[d], &g_xpl[d]);
        }
    }
}

// ---------------- weight packs --------------------------------------------------
__global__ void k_packw1(const float* __restrict__ w) {   // -> [tap][m=128][c=448]
    int i = blockIdx.x * 256 + threadIdx.x;
    if (i >= 9 * 128 * 448) return;
    int c = i % 448; int t2 = i / 448; int m = t2 % 128; int tap = t2 / 128;
    split2(w[(m * 448 + c) * 9 + tap], &g_w1h[i], &g_w1l[i]);
}
__global__ void k_packw2(const float* __restrict__ w) {   // -> [tap][o=448][c=128]
    int i = blockIdx.x * 256 + threadIdx.x;
    if (i >= 9 * 448 * 128) return;
    int c = i % 128; int t2 = i / 128; int o = t2 % 448; int tap = t2 / 448;
    split2(w[(o * 128 + c) * 9 + tap], &g_w2h[i], &g_w2l[i]);
}
__global__ void k_packwq(const float* __restrict__ w1, const float* __restrict__ w2) {
    int i = blockIdx.x * 256 + threadIdx.x;               // weff[m=256][k=384], k=d*3+s
    if (i >= 256 * 384) return;
    int m = i / 384, k = i % 384;
    split2(w1[m * 128 + k / 3] * w2[k % 3], &g_wqh[i], &g_wql[i]);
}
__global__ void k_packwo(const float* __restrict__ w) {   // [o=128][c=128]
    int i = blockIdx.x * 256 + threadIdx.x;
    if (i >= 128 * 128) return;
    split2(w[i], &g_woh[i], &g_wol[i]);
}

// ---------------- 2/7) conv3x3 implicit GEMM, cp.async double-buffered ----------
// NROWS=1: each block does one output row (32 px), M = WARPS*MT*16 out channels.
// smem tile: [rc 102][16 ch] at stride 24 els (48B) -> conflict-free fragment LDS.
template<int CIN, int COUT, int WARPS, int MT, int NT, int MODE>
__global__ void __launch_bounds__(WARPS*32) k_convmma(const float* __restrict__ bias,
                                                      const float* __restrict__ pos) {
    const int THREADS = WARPS * 32;
    const int CHUNKS = CIN / 16;
    __shared__ __nv_bfloat16 sh[2][102 * 24];
    __shared__ __nv_bfloat16 sl[2][102 * 24];
    const __nv_bfloat16* inh = (MODE == 1) ? g_xph : g_o2h;
    const __nv_bfloat16* inl = (MODE == 1) ? g_xpl : g_o2l;
    const __nv_bfloat16* wph = (MODE == 1) ? g_w1h : g_w2h;
    const __nv_bfloat16* wpl = (MODE == 1) ? g_w1l : g_w2l;
    int y0  = blockIdx.x;
    int m0  = blockIdx.y * (WARPS * MT * 16);
    int img = blockIdx.z;
    int tid = threadIdx.x, lane = tid & 31, warp = tid >> 5;
    int q2 = (lane & 3) * 2, gp = lane >> 2;

    float acc[MT][NT][4];
#pragma unroll
    for (int a = 0; a < MT; a++)
#pragma unroll
        for (int b = 0; b < NT; b++)
#pragma unroll
            for (int c = 0; c < 4; c++) acc[a][b][c] = 0.f;

    // stage chunk into buffer buf
    auto stage = [&](int chunk, int buf) {
        int c0 = chunk * 16;
        for (int i = tid; i < 102 * 4; i += THREADS) {
            int arr = i & 1, seg = (i >> 1) & 1, rc = i >> 2;
            int yy = rc / 34, xx = rc % 34;
            size_t src = (((size_t)img * 34 + y0 + yy) * 34 + xx) * CIN + c0 + seg * 8;
            int dst = rc * 24 + seg * 8;
            if (arr) cpasync16(&sl[buf][dst], inl + src);
            else     cpasync16(&sh[buf][dst], inh + src);
        }
    };

    stage(0, 0);
    asm volatile("cp.async.commit_group;\n");

    for (int ch = 0; ch < CHUNKS; ch++) {
        if (ch + 1 < CHUNKS) {
            stage(ch + 1, (ch + 1) & 1);
            asm volatile("cp.async.commit_group;\n");
            asm volatile("cp.async.wait_group 1;\n");
        } else {
            asm volatile("cp.async.wait_group 0;\n");
        }
        __syncthreads();
        int buf = ch & 1;
        int c0 = ch * 16;
#pragma unroll
        for (int tap = 0; tap < 9; tap++) {
            int ky = tap / 3, kx = tap % 3;
            unsigned A[MT][8];
#pragma unroll
            for (int mt = 0; mt < MT; mt++) {
                int m = m0 + (warp * MT + mt) * 16 + gp;
                const __nv_bfloat16* wb = wph + (size_t)(tap * COUT + m) * CIN + c0 + q2;
                const __nv_bfloat16* wl = wpl + (size_t)(tap * COUT + m) * CIN + c0 + q2;
                A[mt][0] = ldb2(wb);     A[mt][1] = ldb2(wb + 8 * CIN);
                A[mt][2] = ldb2(wb + 8); A[mt][3] = ldb2(wb + 8 * CIN + 8);
                A[mt][4] = ldb2(wl);     A[mt][5] = ldb2(wl + 8 * CIN);
                A[mt][6] = ldb2(wl + 8); A[mt][7] = ldb2(wl + 8 * CIN + 8);
            }
#pragma unroll
            for (int nt = 0; nt < NT; nt++) {
                int rc = ky * 34 + nt * 8 + gp + kx;
                int ad = rc * 24 + q2;
                unsigned bh0 = ldb2(&sh[buf][ad]), bh1 = ldb2(&sh[buf][ad + 8]);
                unsigned bl0 = ldb2(&sl[buf][ad]), bl1 = ldb2(&sl[buf][ad + 8]);
#pragma unroll
                for (int mt = 0; mt < MT; mt++) {
                    mma16816(acc[mt][nt], A[mt][0], A[mt][1], A[mt][2], A[mt][3], bh0, bh1);
                    mma16816(acc[mt][nt], A[mt][4], A[mt][5], A[mt][6], A[mt][7], bh0, bh1);
                    mma16816(acc[mt][nt], A[mt][0], A[mt][1], A[mt][2], A[mt][3], bl0, bl1);
                }
            }
        }
        __syncthreads();
    }

#pragma unroll
    for (int mt = 0; mt < MT; mt++) {
        int m = m0 + (warp * MT + mt) * 16 + gp;
        float bv0 = bias[m], bv1 = bias[m + 8];
#pragma unroll
        for (int nt = 0; nt < NT; nt++) {
            int x = nt * 8 + q2;
            float v0 = acc[mt][nt][0] + bv0;
            float v1 = acc[mt][nt][1] + bv0;
            float v2 = acc[mt][nt][2] + bv1;
            float v3 = acc[mt][nt][3] + bv1;
            if (MODE == 1) {
                v0 += pos[m * 1024 + y0 * 32 + x];
                v1 += pos[m * 1024 + y0 * 32 + x + 1];
                v2 += pos[(m + 8) * 1024 + y0 * 32 + x];
                v3 += pos[(m + 8) * 1024 + y0 * 32 + x + 1];
                *reinterpret_cast<float2*>(&g_conv1[((img * 128 + m) * 32 + y0) * 32 + x])     = make_float2(v0, v1);
                *reinterpret_cast<float2*>(&g_conv1[((img * 128 + m + 8) * 32 + y0) * 32 + x]) = make_float2(v2, v3);
            } else {
                int o = m;
                int p1i = o / 56, rem = o % 56, p2i = rem / 7, e = rem % 7;
                size_t base = (((size_t)img * 7 + e) * 256 + y0 * 8 + p1i) * 256;
                g_u[base + x * 8 + p2i]       = v0;
                g_u[base + (x + 1) * 8 + p2i] = v1;
                o = m + 8;
                p1i = o / 56; rem = o % 56; p2i = rem / 7; e = rem % 7;
                base = (((size_t)img * 7 + e) * 256 + y0 * 8 + p1i) * 256;
                g_u[base + x * 8 + p2i]       = v2;
                g_u[base + (x + 1) * 8 + p2i] = v3;
            }
        }
    }
}

// ---------------- 3) group norm -> bf16 hi/lo -----------------------------------
__global__ void k_gnorm(const float* __restrict__ gamma, const float* __restrict__ beta) {
    int b = blockIdx.x >> 4, g = blockIdx.x & 15;
    const int CH = 24576;
    size_t base = (size_t)b * 393216 + (size_t)g * CH;
    int tid = threadIdx.x;
    float s = 0.f, sq = 0.f;
    for (int i = tid; i < CH; i += 256) {
        float v = g_conv1[base + i];
        s += v; sq += v * v;
    }
#pragma unroll
    for (int off = 16; off; off >>= 1) {
        s  += __shfl_xor_sync(0xffffffffu, s,  off);
        sq += __shfl_xor_sync(0xffffffffu, sq, off);
    }
    __shared__ float rs[8], rq[8];
    int w = tid >> 5, lane = tid & 31;
    if (!lane) { rs[w] = s; rq[w] = sq; }
    __syncthreads();
    s = 0.f; sq = 0.f;
#pragma unroll
    for (int i = 0; i < 8; i++) { s += rs[i]; sq += rq[i]; }
    float mean = s / (float)CH;
    float var  = sq / (float)CH - mean * mean;
    float inv  = rsqrtf(var + EPSV);
    for (int i = tid; i < CH; i += 256) {
        int dch = g * 8 + i / 3072;
        float v = (g_conv1[base + i] - mean) * inv * gamma[dch] + beta[dch];
        split2(v, &g_xnh[base + i], &g_xnl[base + i]);
    }
}

// ---------------- 4) q GEMM via mma: C[4096][256] = xn[4096][384] @ weff^T ------
__global__ void __launch_bounds__(256) k_qmma(const float* __restrict__ b1,
                                              const float* __restrict__ w2,
                                              const float* __restrict__ b2) {
    int n0 = blockIdx.x * 128, o0 = blockIdx.y * 64;
    int tid = threadIdx.x, lane = tid & 31, warp = tid >> 5;
    int q2 = (lane & 3) * 2, gp = lane >> 2;
    float acc[8][4];
#pragma unroll
    for (int a = 0; a < 8; a++)
#pragma unroll
        for (int c = 0; c < 4; c++) acc[a][c] = 0.f;

    const __nv_bfloat16* Ah = g_xnh + (size_t)(n0 + warp * 16 + gp) * 384 + q2;
    const __nv_bfloat16* Al = g_xnl + (size_t)(n0 + warp * 16 + gp) * 384 + q2;

    for (int kk = 0; kk < 384; kk += 16) {
        unsigned a0 = ldb2(Ah + kk),            a1 = ldb2(Ah + 8 * 384 + kk);
        unsigned a2 = ldb2(Ah + kk + 8),        a3 = ldb2(Ah + 8 * 384 + kk + 8);
        unsigned l0 = ldb2(Al + kk),            l1 = ldb2(Al + 8 * 384 + kk);
        unsigned l2 = ldb2(Al + kk + 8),        l3 = ldb2(Al + 8 * 384 + kk + 8);
#pragma unroll
        for (int nt = 0; nt < 8; nt++) {
            const __nv_bfloat16* Bh = g_wqh + (size_t)(o0 + nt * 8 + gp) * 384 + q2 + kk;
            const __nv_bfloat16* Bl = g_wql + (size_t)(o0 + nt * 8 + gp) * 384 + q2 + kk;
            unsigned bh0 = ldb2(Bh), bh1 = ldb2(Bh + 8);
            unsigned bl0 = ldb2(Bl), bl1 = ldb2(Bl + 8);
            mma16816(acc[nt], a0, a1, a2, a3, bh0, bh1);
            mma16816(acc[nt], l0, l1, l2, l3, bh0, bh1);
            mma16816(acc[nt], a0, a1, a2, a3, bl0, bl1);
        }
    }
    float sws = w2[0] + w2[1] + w2[2];
    float fb = b2[0];
    int n = n0 + warp * 16 + gp;
#pragma unroll
    for (int nt = 0; nt < 8; nt++) {
        int o = o0 + nt * 8 + q2;
        g_q[n * 256 + o]           = acc[nt][0] + b1[o] * sws + fb;
        g_q[n * 256 + o + 1]       = acc[nt][1] + b1[o + 1] * sws + fb;
        g_q[(n + 8) * 256 + o]     = acc[nt][2] + b1[o] * sws + fb;
        g_q[(n + 8) * 256 + o + 1] = acc[nt][3] + b1[o + 1] * sws + fb;
    }
}

// ---------------- 5) attention (one block per row r) ----------------------------
__global__ void k_attn(const float* __restrict__ kc, const float* __restrict__ vc) {
    int r = blockIdx.x;
    int tid = threadIdx.x;     // 128
    int w = tid >> 5, lane = tid & 31;
    __shared__ float sq[64];
    __shared__ float se[128];
    __shared__ float red[4], red2[4];
    __shared__ float oacc[4][32];

    if (tid < 64) sq[tid] = g_q[r * 64 + tid];
    __syncthreads();

    const float4* krow = (const float4*)(kc + (size_t)r * 8192 + (size_t)tid * 64);
    float dot = 0.f;
#pragma unroll
    for (int i = 0; i < 16; i++) {
        float4 kv = krow[i];
        dot += kv.x * sq[i * 4] + kv.y * sq[i * 4 + 1] + kv.z * sq[i * 4 + 2] + kv.w * sq[i * 4 + 3];
    }
    dot *= 0.125f;

    float m = dot;
#pragma unroll
    for (int off = 16; off; off >>= 1) m = fmaxf(m, __shfl_xor_sync(0xffffffffu, m, off));
    if (!lane) red[w] = m;
    __syncthreads();
    m = fmaxf(fmaxf(red[0], red[1]), fmaxf(red[2], red[3]));

    float e = __expf(dot - m);
    se[tid] = e;
    float s = e;
#pragma unroll
    for (int off = 16; off; off >>= 1) s += __shfl_xor_sync(0xffffffffu, s, off);
    if (!lane) red2[w] = s;
    __syncthreads();
    float inv = 1.f / (red2[0] + red2[1] + red2[2] + red2[3]);

    const float* vbase = vc + (size_t)r * 4096;
    float a = 0.f;
#pragma unroll 4
    for (int li = 0; li < 32; li++) {
        int l = w * 32 + li;
        a = fmaf(se[l], vbase[l * 32 + lane], a);
    }
    oacc[w][lane] = a;
    __syncthreads();
    if (tid < 32) {
        float tot = (oacc[0][tid] + oacc[1][tid] + oacc[2][tid] + oacc[3][tid]) * inv;
        int lin = (r & 4095) * 128 + (r >> 12) * 32 + tid;   // (Nq,DC) flat index
        int bb = lin >> 17;
        int C  = (lin >> 10) & 127;
        int hw = lin & 1023;
        size_t d = ((size_t)(bb * 1024 + hw)) * 128 + C;     // transposed [b][hw][C]
        split2(tot, &g_oah[d], &g_oal[d]);
    }
}

// ---------------- 6) out projection via mma -> channel-last padded conv2 input --
__global__ void __launch_bounds__(256) k_omma(const float* __restrict__ bias) {
    int hw0 = blockIdx.x * 64, b = blockIdx.y;
    int tid = threadIdx.x, lane = tid & 31, warp = tid >> 5;
    int q2 = (lane & 3) * 2, gp = lane >> 2;
    float acc[8][4];
#pragma unroll
    for (int a = 0; a < 8; a++)
#pragma unroll
        for (int c = 0; c < 4; c++) acc[a][c] = 0.f;

    const __nv_bfloat16* Ah = g_woh + (size_t)(warp * 16 + gp) * 128 + q2;
    const __nv_bfloat16* Al = g_wol + (size_t)(warp * 16 + gp) * 128 + q2;

    for (int kk = 0; kk < 128; kk += 16) {
        unsigned a0 = ldb2(Ah + kk),            a1 = ldb2(Ah + 8 * 128 + kk);
        unsigned a2 = ldb2(Ah + kk + 8),        a3 = ldb2(Ah + 8 * 128 + kk + 8);
        unsigned l0 = ldb2(Al + kk),            l1 = ldb2(Al + 8 * 128 + kk);
        unsigned l2 = ldb2(Al + kk + 8),        l3 = ldb2(Al + 8 * 128 + kk + 8);
#pragma unroll
        for (int nt = 0; nt < 8; nt++) {
            const __nv_bfloat16* Bh = g_oah + ((size_t)b * 1024 + hw0 + nt * 8 + gp) * 128 + q2 + kk;
            const __nv_bfloat16* Bl = g_oal + ((size_t)b * 1024 + hw0 + nt * 8 + gp) * 128 + q2 + kk;
            unsigned bh0 = ldb2(Bh), bh1 = ldb2(Bh + 8);
            unsigned bl0 = ldb2(Bl), bl1 = ldb2(Bl + 8);
            mma16816(acc[nt], a0, a1, a2, a3, bh0, bh1);
            mma16816(acc[nt], l0, l1, l2, l3, bh0, bh1);
            mma16816(acc[nt], a0, a1, a2, a3, bl0, bl1);
        }
    }
    int o = warp * 16 + gp;
    float bv0 = bias[o], bv1 = bias[o + 8];
#pragma unroll
    for (int nt = 0; nt < 8; nt++) {
        int hw = hw0 + nt * 8 + q2;
        int y = hw >> 5, x = hw & 31;
        size_t d0 = (((size_t)b * 34 + y + 1) * 34 + x + 1) * 128;
        size_t d1 = d0 + 128;                                   // x+1 neighbor
        split2(acc[nt][0] + bv0, &g_o2h[d0 + o],     &g_o2l[d0 + o]);
        split2(acc[nt][1] + bv0, &g_o2h[d1 + o],     &g_o2l[d1 + o]);
        split2(acc[nt][2] + bv1, &g_o2h[d0 + o + 8], &g_o2l[d0 + o + 8]);
        split2(acc[nt][3] + bv1, &g_o2h[d1 + o + 8], &g_o2l[d1 + o + 8]);
    }
}

// ---------------- 8) modulation -------------------------------------------------
__global__ void k_cmod(const float* __restrict__ emb, const float* __restrict__ mw,
                       const float* __restrict__ mb) {
    int t = threadIdx.x;
    if (t >= 56) return;
    int b = t / 14, j = t % 14;
    float acc = mb[j];
    for (int i = 0; i < 256; i++) {
        float v = emb[b * 256 + i];
        float sil = v / (1.f + __expf(-v));
        acc = fmaf(sil, mw[j * 256 + i], acc);
    }
    g_cmod[t] = acc;
}

// ---------------- 9/10) per-batch stats of u ------------------------------------
__global__ void k_upart() {
    int b = blockIdx.y, blk = blockIdx.x;
    size_t base = (size_t)b * 458752 + (size_t)blk * 14336;
    int tid = threadIdx.x;
    float s = 0.f, sq = 0.f;
    for (int i = tid; i < 14336; i += 256) {
        float v = g_u[base + i];
        s += v; sq += v * v;
    }
#pragma unroll
    for (int off = 16; off; off >>= 1) {
        s  += __shfl_xor_sync(0xffffffffu, s,  off);
        sq += __shfl_xor_sync(0xffffffffu, sq, off);
    }
    __shared__ float rs[8], rq[8];
    int w = tid >> 5, lane = tid & 31;
    if (!lane) { rs[w] = s; rq[w] = sq; }
    __syncthreads();
    if (tid == 0) {
        float ts = 0.f, tq = 0.f;
#pragma unroll
        for (int i = 0; i < 8; i++) { ts += rs[i]; tq += rq[i]; }
        g_psum[b * 32 + blk] = ts;
        g_psq [b * 32 + blk] = tq;
    }
}
__global__ void k_ucomb() {
    int b = threadIdx.x;
    if (b < 4) {
        float s = 0.f, sq = 0.f;
        for (int i = 0; i < 32; i++) { s += g_psum[b * 32 + i]; sq += g_psq[b * 32 + i]; }
        float mean = s / 458752.f;
        float var  = sq / 458752.f - mean * mean;
        g_stats[b * 2]     = mean;
        g_stats[b * 2 + 1] = rsqrtf(var + EPSV);
    }
}

// ---------------- 11) final fused elementwise -----------------------------------
__global__ void k_final(const float* __restrict__ ew, const float* __restrict__ eb,
                        const float* __restrict__ fw, const float* __restrict__ fb,
                        float* __restrict__ out) {
    int b = blockIdx.y;
    int p = blockIdx.x * 256 + threadIdx.x;
    __shared__ float s_ew[98], s_eb[14], s_fw[49], s_fb[7], s_sc[7], s_sh[7];
    __shared__ float s_mean, s_istd;
    int t = threadIdx.x;
    if (t < 98) s_ew[t] = ew[t];
    if (t < 49) s_fw[t] = fw[t];
    if (t < 14) s_eb[t] = eb[t];
    if (t < 7)  { s_fb[t] = fb[t]; s_sc[t] = g_cmod[b * 14 + t]; s_sh[t] = g_cmod[b * 14 + 7 + t]; }
    if (t == 0) { s_mean = g_stats[b * 2]; s_istd = g_stats[b * 2 + 1]; }
    __syncthreads();

    float mean = s_mean, istd = s_istd;
    float uv[7], un[7];
#pragma unroll
    for (int e = 0; e < 7; e++) uv[e] = g_u[((size_t)b * 7 + e) * 65536 + p];
#pragma unroll
    for (int e = 0; e < 7; e++) un[e] = (uv[e] - mean) * istd * (1.f + s_sc[e]) + s_sh[e];

    float en[14];
#pragma unroll
    for (int j = 0; j < 14; j++) {
        float a = s_eb[j];
#pragma unroll
        for (int e = 0; e < 7; e++) a = fmaf(s_ew[j * 7 + e], un[e], a);
        en[j] = a;
    }
    float hf[7];
#pragma unroll
    for (int e = 0; e < 7; e++) hf[e] = geluf(un[e]) + en[e] * geluf(en[7 + e]);

#pragma unroll
    for (int o = 0; o < 7; o++) {
        float a = s_fb[o];
#pragma unroll
        for (int e = 0; e < 7; e++) a = fmaf(s_fw[o * 7 + e], hf[e], a);
        out[((size_t)b * 7 + o) * 65536 + p] = a + uv[o];
    }
}

// ---------------- launch --------------------------------------------------------
extern "C" void kernel_launch(void* const* d_in, const int* in_sizes, int n_in,
                              void* d_out, int out_size) {
    const float* x         = (const float*)d_in[0];
    const float* k_cond    = (const float*)d_in[1];
    const float* v_cond    = (const float*)d_in[2];
    const float* emb       = (const float*)d_in[3];
    const float* pos_embed = (const float*)d_in[4];
    const float* patch_w   = (const float*)d_in[5];
    const float* patch_b   = (const float*)d_in[6];
    const float* gn_gamma  = (const float*)d_in[7];
    const float* gn_beta   = (const float*)d_in[8];
    const float* fc1q_w    = (const float*)d_in[9];
    const float* fc1q_b    = (const float*)d_in[10];
    const float* fc2q_w    = (const float*)d_in[11];
    const float* fc2q_b    = (const float*)d_in[12];
    const float* outproj_w = (const float*)d_in[13];
    const float* outproj_b = (const float*)d_in[14];
    const float* unpatch_w = (const float*)d_in[15];
    const float* unpatch_b = (const float*)d_in[16];
    const float* mod_w     = (const float*)d_in[17];
    const float* mod_b     = (const float*)d_in[18];
    const float* enlarge_w = (const float*)d_in[19];
    const float* enlarge_b = (const float*)d_in[20];
    const float* ff2_w     = (const float*)d_in[21];
    const float* ff2_b     = (const float*)d_in[22];
    float* out = (float*)d_out;

    // launch order arranged so the ncu capture slot (4th launch) hits conv1
    k_pack  <<<dim3(32, 12), 256>>>(x);
    k_packw1<<<(9*128*448 + 255) / 256, 256>>>(patch_w);
    k_packwq<<<384, 256>>>(fc1q_w, fc2q_w);
    k_convmma<448, 128, 4, 2, 4, 1><<<dim3(32, 1, 12), 128>>>(patch_b, pos_embed);
    k_gnorm<<<64, 256>>>(gn_gamma, gn_beta);
    k_qmma<<<dim3(32, 4), 256>>>(fc1q_b, fc2q_w, fc2q_b);
    k_packwo<<<64, 256>>>(outproj_w);
    k_attn<<<16384, 128>>>(k_cond, v_cond);
    k_omma<<<dim3(16, 4), 256>>>(outproj_b);
    k_packw2<<<(9*448*128 + 255) / 256, 256>>>(unpatch_w);
    k_convmma<128, 448, 7, 2, 4, 2><<<dim3(32, 2, 4), 224>>>(unpatch_b, (const float*)0);
    k_cmod<<<1, 64>>>(emb, mod_w, mod_b);
    k_upart<<<dim3(32, 4), 256>>>();
    k_ucomb<<<1, 32>>>();
    k_final<<<dim3(256, 4), 256>>>(enlarge_w, enlarge_b, ff2_w, ff2_b, out);
}

// round 7
// speedup vs baseline: 1.1707x; 1.1707x over previous
#include <cuda_runtime.h>
#include <cuda_bf16.h>
#include <math.h>

#define EPSV 1e-5f

// ---------------- scratch (__device__ globals; zero-init borders load-bearing) --
// conv inputs channel-last padded, hi/lo interleaved per channel-pair:
// [img][y 34][x 34][C/2 groups][4 els: hi_c, hi_c+1, lo_c, lo_c+1]
__device__ __nv_bfloat16 g_xp[12*34*34*896];
__device__ __nv_bfloat16 g_o2[4*34*34*256];
// fragment-packed conv weights: [tap][mtile][chunk][half(hi/lo)][lane] uint4
__device__ uint4 g_w1p[9*8*28*64];
__device__ uint4 g_w2p[9*28*8*64];
__device__ __nv_bfloat16 g_wqh[256*384];
__device__ __nv_bfloat16 g_wql[256*384];
__device__ __nv_bfloat16 g_woh[128*128];
__device__ __nv_bfloat16 g_wol[128*128];
__device__ float         g_conv1[12*128*1024];
__device__ float         g_c1b  [12*128*1024];   // conv1 K-split partial
__device__ __nv_bfloat16 g_xnh[12*128*1024];
__device__ __nv_bfloat16 g_xnl[12*128*1024];
__device__ float         g_q[4096*256];
__device__ __nv_bfloat16 g_oah[4*1024*128];      // attn out transposed [b][hw][C]
__device__ __nv_bfloat16 g_oal[4*1024*128];
__device__ float         g_u [4*7*65536];
__device__ float         g_ub[4*7*65536];        // conv2 K-split partial
__device__ float g_cmod[64];
__device__ float g_psum[128], g_psq[128], g_stats[8];

// ---------------- helpers ----------------
__device__ __forceinline__ void split2(float v, __nv_bfloat16* h, __nv_bfloat16* l) {
    __nv_bfloat16 hh = __float2bfloat16(v);
    *h = hh;
    *l = __float2bfloat16(v - __bfloat162float(hh));
}
__device__ __forceinline__ void split2i(float v, __nv_bfloat16* p) {  // interleaved: hi at p, lo at p+2
    __nv_bfloat16 hh = __float2bfloat16(v);
    p[0] = hh;
    p[2] = __float2bfloat16(v - __bfloat162float(hh));
}
__device__ __forceinline__ float geluf(float v) {
    return 0.5f * v * (1.0f + erff(v * 0.70710678118654752f));
}
__device__ __forceinline__ unsigned ldb2(const __nv_bfloat16* p) {
    return *reinterpret_cast<const unsigned*>(p);
}
__device__ __forceinline__ void mma16816(float* c, unsigned a0, unsigned a1, unsigned a2, unsigned a3,
                                         unsigned b0, unsigned b1) {
    asm volatile("mma.sync.aligned.m16n8k16.row.col.f32.bf16.bf16.f32 "
        "{%0,%1,%2,%3}, {%4,%5,%6,%7}, {%8,%9}, {%0,%1,%2,%3};\n"
        : "+f"(c[0]), "+f"(c[1]), "+f"(c[2]), "+f"(c[3])
        : "r"(a0), "r"(a1), "r"(a2), "r"(a3), "r"(b0), "r"(b1));
}
__device__ __forceinline__ void cpasync16(void* dst_smem, const void* src) {
    unsigned sa = (unsigned)__cvta_generic_to_shared(dst_smem);
    asm volatile("cp.async.cg.shared.global [%0], [%1], 16;\n" :: "r"(sa), "l"(src));
}

// ---------------- 1) pack x -> interleaved channel-last padded ------------------
__global__ void k_pack(const float* __restrict__ x) {
    __shared__ float s[28 * 256];
    int y = blockIdx.x, nimg = blockIdx.y;   // nimg = b*3 + s
    int tid = threadIdx.x;
#pragma unroll
    for (int half = 0; half < 2; half++) {
        __syncthreads();
        for (int i = tid; i < 28 * 64; i += 256) {
            int row = i >> 6, col4 = i & 63;         // row = e*4 + pp
            int e = row >> 2, pp = row & 3;
            int p1 = half * 4 + pp;
            const float4* src = reinterpret_cast<const float4*>(
                x + (((size_t)nimg * 7 + e) * 256 + y * 8 + p1) * 256) + col4;
            reinterpret_cast<float4*>(s)[row * 64 + col4] = *src;
        }
        __syncthreads();
        for (int i = tid; i < 32 * 224; i += 256) {
            int xq = i / 224, cl = i % 224;
            int p1l = cl / 56, rem = cl % 56, p2 = rem / 7, e = rem % 7;
            float v = s[(e * 4 + p1l) * 256 + xq * 8 + p2];
            int c = half * 224 + cl;
            size_t d = (((size_t)nimg * 34 + y + 1) * 34 + xq + 1) * 896
                     + ((c >> 1) << 2) + (c & 1);
            split2i(v, &g_xp[d]);
        }
    }
}

// ---------------- conv weight fragment packer -----------------------------------
template<int CIN, int MTILES, int CHUNKS, int MODE>
__global__ void k_packwc(const float* __restrict__ w) {
    uint4* dst = (MODE == 1) ? g_w1p : g_w2p;
    int i = blockIdx.x * 256 + threadIdx.x;
    if (i >= 9 * MTILES * CHUNKS * 64) return;
    int lane = i & 31;
    int half = (i >> 5) & 1;
    int idx  = i >> 6;
    int chunk = idx % CHUNKS;
    int mtile = (idx / CHUNKS) % MTILES;
    int tap   = idx / (CHUNKS * MTILES);
    int gp = lane >> 2, q2 = (lane & 3) * 2;
    unsigned r[4];
#pragma unroll
    for (int rr = 0; rr < 4; rr++) {
        int m = mtile * 16 + gp + ((rr & 1) << 3);
        int c = chunk * 16 + q2 + ((rr & 2) << 2);
        float w0 = w[((size_t)m * CIN + c) * 9 + tap];
        float w1 = w[((size_t)m * CIN + c + 1) * 9 + tap];
        __nv_bfloat16 h0 = __float2bfloat16(w0), h1 = __float2bfloat16(w1);
        if (half) {
            h0 = __float2bfloat16(w0 - __bfloat162float(h0));
            h1 = __float2bfloat16(w1 - __bfloat162float(h1));
        }
        unsigned short u0 = *reinterpret_cast<unsigned short*>(&h0);
        unsigned short u1 = *reinterpret_cast<unsigned short*>(&h1);
        r[rr] = (unsigned)u0 | ((unsigned)u1 << 16);
    }
    dst[i] = make_uint4(r[0], r[1], r[2], r[3]);
}

__global__ void k_packwq(const float* __restrict__ w1, const float* __restrict__ w2) {
    int i = blockIdx.x * 256 + threadIdx.x;               // weff[m=256][k=384], k=d*3+s
    if (i >= 256 * 384) return;
    int m = i / 384, k = i % 384;
    split2(w1[m * 128 + k / 3] * w2[k % 3], &g_wqh[i], &g_wql[i]);
}
__global__ void k_packwo(const float* __restrict__ w) {   // [o=128][c=128]
    int i = blockIdx.x * 256 + threadIdx.x;
    if (i >= 128 * 128) return;
    split2(w[i], &g_woh[i], &g_wol[i]);
}

// ---------------- 2/7) conv3x3 implicit GEMM ------------------------------------
// NT=8: 2 output rows per block. K-split 2 via blockIdx.y (MODE2 also m-split).
// smem: [pix 136][32 els], 16B segs XOR-swizzled by (pix&3) -> conflict-free LDS.64.
template<int CIN, int COUT, int WARPS, int MT, int NT, int MODE>
__global__ void __launch_bounds__(WARPS*32) k_convmma(const float* __restrict__ bias,
                                                      const float* __restrict__ pos) {
    const int THREADS = WARPS * 32;
    const int TOTCH = CIN / 16;
    const int KCH   = TOTCH / 2;
    const int MTILES = COUT / 16;
    const int PIX = (NT / 4 + 2) * 34;          // 136
    __shared__ __align__(16) __nv_bfloat16 sbuf[2][PIX * 32];

    const __nv_bfloat16* inp = (MODE == 1) ? g_xp : g_o2;
    const uint4* wp = (MODE == 1) ? g_w1p : g_w2p;

    int kpart, mtb;
    if (MODE == 1) { kpart = blockIdx.y; mtb = 0; }
    else           { kpart = blockIdx.y & 1; mtb = (blockIdx.y >> 1) * (WARPS * MT); }
    int y0  = blockIdx.x * (NT / 4);
    int img = blockIdx.z;
    int tid = threadIdx.x, lane = tid & 31, warp = tid >> 5;
    int gp = lane >> 2, q2 = (lane & 3) * 2;
    int ck0 = kpart * KCH;

    float acc[MT][NT][4];
#pragma unroll
    for (int a = 0; a < MT; a++)
#pragma unroll
        for (int b = 0; b < NT; b++)
#pragma unroll
            for (int c = 0; c < 4; c++) acc[a][b][c] = 0.f;

    size_t pixbase = ((size_t)img * 1156 + (size_t)y0 * 34) * (2 * CIN);

    auto stage = [&](int chunk, int buf) {
        for (int p = tid; p < PIX; p += THREADS) {
            size_t sg = pixbase + (size_t)p * (2 * CIN) + chunk * 32;
            int dbase = p * 32;
            int sw = p & 3;
#pragma unroll
            for (int s4 = 0; s4 < 4; s4++)
                cpasync16(&sbuf[buf][dbase + ((s4 ^ sw) << 3)], inp + sg + s4 * 8);
        }
    };

    stage(ck0, 0);
    asm volatile("cp.async.commit_group;\n");

    for (int ck = 0; ck < KCH; ck++) {
        if (ck + 1 < KCH) {
            stage(ck0 + ck + 1, (ck + 1) & 1);
            asm volatile("cp.async.commit_group;\n");
            asm volatile("cp.async.wait_group 1;\n");
        } else {
            asm volatile("cp.async.wait_group 0;\n");
        }
        __syncthreads();
        const __nv_bfloat16* sb = sbuf[ck & 1];
        int chunk = ck0 + ck;
#pragma unroll
        for (int tap = 0; tap < 9; tap++) {
            const int ky = tap / 3, kx = tap % 3;
            uint4 Ah[MT], Al[MT];
#pragma unroll
            for (int mt = 0; mt < MT; mt++) {
                const uint4* pa = wp + ((((size_t)tap * MTILES + mtb + warp * MT + mt) * TOTCH + chunk) << 6) + lane;
                Ah[mt] = pa[0];
                Al[mt] = pa[32];
            }
#pragma unroll
            for (int nt = 0; nt < NT; nt++) {
                int n  = nt * 8 + gp;
                int rc = (ky + (n >> 5)) * 34 + (n & 31) + kx;
                int sw = rc & 3;
                int hb = rc * 32 + ((q2 & 2) << 1);
                int s1 = (q2 >> 2) ^ sw;
                int s2 = ((q2 >> 2) + 2) ^ sw;
                uint2 f1 = *reinterpret_cast<const uint2*>(&sb[hb + (s1 << 3)]);   // (bh0, bl0)
                uint2 f2 = *reinterpret_cast<const uint2*>(&sb[hb + (s2 << 3)]);   // (bh1, bl1)
#pragma unroll
                for (int mt = 0; mt < MT; mt++) {
                    mma16816(acc[mt][nt], Ah[mt].x, Ah[mt].y, Ah[mt].z, Ah[mt].w, f1.x, f2.x);
                    mma16816(acc[mt][nt], Al[mt].x, Al[mt].y, Al[mt].z, Al[mt].w, f1.x, f2.x);
                    mma16816(acc[mt][nt], Ah[mt].x, Ah[mt].y, Ah[mt].z, Ah[mt].w, f1.y, f2.y);
                }
            }
        }
        __syncthreads();
    }

#pragma unroll
    for (int mt = 0; mt < MT; mt++) {
        int m = (mtb + warp * MT + mt) * 16 + gp;
        float bv0 = (kpart == 0) ? bias[m] : 0.f;
        float bv1 = (kpart == 0) ? bias[m + 8] : 0.f;
#pragma unroll
        for (int nt = 0; nt < NT; nt++) {
            int n  = nt * 8 + q2;
            int yo = y0 + (n >> 5);
            int x  = n & 31;
            float v0 = acc[mt][nt][0] + bv0;
            float v1 = acc[mt][nt][1] + bv0;
            float v2 = acc[mt][nt][2] + bv1;
            float v3 = acc[mt][nt][3] + bv1;
            if (MODE == 1) {
                float* dst = (kpart == 0) ? g_conv1 : g_c1b;
                if (kpart == 0) {
                    v0 += pos[m * 1024 + yo * 32 + x];
                    v1 += pos[m * 1024 + yo * 32 + x + 1];
                    v2 += pos[(m + 8) * 1024 + yo * 32 + x];
                    v3 += pos[(m + 8) * 1024 + yo * 32 + x + 1];
                }
                *reinterpret_cast<float2*>(&dst[((img * 128 + m) * 32 + yo) * 32 + x])     = make_float2(v0, v1);
                *reinterpret_cast<float2*>(&dst[((img * 128 + m + 8) * 32 + yo) * 32 + x]) = make_float2(v2, v3);
            } else {
                float* dst = (kpart == 0) ? g_u : g_ub;
                int o = m;
                int p1i = o / 56, rem = o % 56, p2i = rem / 7, e = rem % 7;
                size_t base = (((size_t)img * 7 + e) * 256 + yo * 8 + p1i) * 256;
                dst[base + x * 8 + p2i]       = v0;
                dst[base + (x + 1) * 8 + p2i] = v1;
                o = m + 8;
                p1i = o / 56; rem = o % 56; p2i = rem / 7; e = rem % 7;
                base = (((size_t)img * 7 + e) * 256 + yo * 8 + p1i) * 256;
                dst[base + x * 8 + p2i]       = v2;
                dst[base + (x + 1) * 8 + p2i] = v3;
            }
        }
    }
}

// ---------------- 3) group norm (sums K-split partials) -> bf16 hi/lo -----------
__global__ void k_gnorm(const float* __restrict__ gamma, const float* __restrict__ beta) {
    int b = blockIdx.x >> 4, g = blockIdx.x & 15;
    const int CH = 24576;
    size_t base = (size_t)b * 393216 + (size_t)g * CH;
    int tid = threadIdx.x;
    float s = 0.f, sq = 0.f;
    for (int i = tid; i < CH; i += 256) {
        float v = g_conv1[base + i] + g_c1b[base + i];
        s += v; sq += v * v;
    }
#pragma unroll
    for (int off = 16; off; off >>= 1) {
        s  += __shfl_xor_sync(0xffffffffu, s,  off);
        sq += __shfl_xor_sync(0xffffffffu, sq, off);
    }
    __shared__ float rs[8], rq[8];
    int w = tid >> 5, lane = tid & 31;
    if (!lane) { rs[w] = s; rq[w] = sq; }
    __syncthreads();
    s = 0.f; sq = 0.f;
#pragma unroll
    for (int i = 0; i < 8; i++) { s += rs[i]; sq += rq[i]; }
    float mean = s / (float)CH;
    float var  = sq / (float)CH - mean * mean;
    float inv  = rsqrtf(var + EPSV);
    for (int i = tid; i < CH; i += 256) {
        int dch = g * 8 + i / 3072;
        float v = ((g_conv1[base + i] + g_c1b[base + i]) - mean) * inv * gamma[dch] + beta[dch];
        split2(v, &g_xnh[base + i], &g_xnl[base + i]);
    }
}

// ---------------- 4) q GEMM via mma: C[4096][256] = xn[4096][384] @ weff^T ------
__global__ void __launch_bounds__(256) k_qmma(const float* __restrict__ b1,
                                              const float* __restrict__ w2,
                                              const float* __restrict__ b2) {
    int n0 = blockIdx.x * 128, o0 = blockIdx.y * 64;
    int tid = threadIdx.x, lane = tid & 31, warp = tid >> 5;
    int q2 = (lane & 3) * 2, gp = lane >> 2;
    float acc[8][4];
#pragma unroll
    for (int a = 0; a < 8; a++)
#pragma unroll
        for (int c = 0; c < 4; c++) acc[a][c] = 0.f;

    const __nv_bfloat16* Ah = g_xnh + (size_t)(n0 + warp * 16 + gp) * 384 + q2;
    const __nv_bfloat16* Al = g_xnl + (size_t)(n0 + warp * 16 + gp) * 384 + q2;

    for (int kk = 0; kk < 384; kk += 16) {
        unsigned a0 = ldb2(Ah + kk),            a1 = ldb2(Ah + 8 * 384 + kk);
        unsigned a2 = ldb2(Ah + kk + 8),        a3 = ldb2(Ah + 8 * 384 + kk + 8);
        unsigned l0 = ldb2(Al + kk),            l1 = ldb2(Al + 8 * 384 + kk);
        unsigned l2 = ldb2(Al + kk + 8),        l3 = ldb2(Al + 8 * 384 + kk + 8);
#pragma unroll
        for (int nt = 0; nt < 8; nt++) {
            const __nv_bfloat16* Bh = g_wqh + (size_t)(o0 + nt * 8 + gp) * 384 + q2 + kk;
            const __nv_bfloat16* Bl = g_wql + (size_t)(o0 + nt * 8 + gp) * 384 + q2 + kk;
            unsigned bh0 = ldb2(Bh), bh1 = ldb2(Bh + 8);
            unsigned bl0 = ldb2(Bl), bl1 = ldb2(Bl + 8);
            mma16816(acc[nt], a0, a1, a2, a3, bh0, bh1);
            mma16816(acc[nt], l0, l1, l2, l3, bh0, bh1);
            mma16816(acc[nt], a0, a1, a2, a3, bl0, bl1);
        }
    }
    float sws = w2[0] + w2[1] + w2[2];
    float fb = b2[0];
    int n = n0 + warp * 16 + gp;
#pragma unroll
    for (int nt = 0; nt < 8; nt++) {
        int o = o0 + nt * 8 + q2;
        g_q[n * 256 + o]           = acc[nt][0] + b1[o] * sws + fb;
        g_q[n * 256 + o + 1]       = acc[nt][1] + b1[o + 1] * sws + fb;
        g_q[(n + 8) * 256 + o]     = acc[nt][2] + b1[o] * sws + fb;
        g_q[(n + 8) * 256 + o + 1] = acc[nt][3] + b1[o + 1] * sws + fb;
    }
}

// ---------------- 5) attention (one block per row r) ----------------------------
__global__ void k_attn(const float* __restrict__ kc, const float* __restrict__ vc) {
    int r = blockIdx.x;
    int tid = threadIdx.x;     // 128
    int w = tid >> 5, lane = tid & 31;
    __shared__ float sq[64];
    __shared__ float se[128];
    __shared__ float red[4], red2[4];
    __shared__ float oacc[4][32];

    if (tid < 64) sq[tid] = g_q[r * 64 + tid];
    __syncthreads();

    const float4* krow = (const float4*)(kc + (size_t)r * 8192 + (size_t)tid * 64);
    float dot = 0.f;
#pragma unroll
    for (int i = 0; i < 16; i++) {
        float4 kv = krow[i];
        dot += kv.x * sq[i * 4] + kv.y * sq[i * 4 + 1] + kv.z * sq[i * 4 + 2] + kv.w * sq[i * 4 + 3];
    }
    dot *= 0.125f;

    float m = dot;
#pragma unroll
    for (int off = 16; off; off >>= 1) m = fmaxf(m, __shfl_xor_sync(0xffffffffu, m, off));
    if (!lane) red[w] = m;
    __syncthreads();
    m = fmaxf(fmaxf(red[0], red[1]), fmaxf(red[2], red[3]));

    float e = __expf(dot - m);
    se[tid] = e;
    float s = e;
#pragma unroll
    for (int off = 16; off; off >>= 1) s += __shfl_xor_sync(0xffffffffu, s, off);
    if (!lane) red2[w] = s;
    __syncthreads();
    float inv = 1.f / (red2[0] + red2[1] + red2[2] + red2[3]);

    const float* vbase = vc + (size_t)r * 4096;
    float a = 0.f;
#pragma unroll 4
    for (int li = 0; li < 32; li++) {
        int l = w * 32 + li;
        a = fmaf(se[l], vbase[l * 32 + lane], a);
    }
    oacc[w][lane] = a;
    __syncthreads();
    if (tid < 32) {
        float tot = (oacc[0][tid] + oacc[1][tid] + oacc[2][tid] + oacc[3][tid]) * inv;
        int lin = (r & 4095) * 128 + (r >> 12) * 32 + tid;   // (Nq,DC) flat index
        int bb = lin >> 17;
        int C  = (lin >> 10) & 127;
        int hw = lin & 1023;
        size_t d = ((size_t)(bb * 1024 + hw)) * 128 + C;     // transposed [b][hw][C]
        split2(tot, &g_oah[d], &g_oal[d]);
    }
}

// ---------------- 6) out projection via mma -> interleaved conv2 input ----------
__global__ void __launch_bounds__(256) k_omma(const float* __restrict__ bias) {
    int hw0 = blockIdx.x * 64, b = blockIdx.y;
    int tid = threadIdx.x, lane = tid & 31, warp = tid >> 5;
    int q2 = (lane & 3) * 2, gp = lane >> 2;
    float acc[8][4];
#pragma unroll
    for (int a = 0; a < 8; a++)
#pragma unroll
        for (int c = 0; c < 4; c++) acc[a][c] = 0.f;

    const __nv_bfloat16* Ah = g_woh + (size_t)(warp * 16 + gp) * 128 + q2;
    const __nv_bfloat16* Al = g_wol + (size_t)(warp * 16 + gp) * 128 + q2;

    for (int kk = 0; kk < 128; kk += 16) {
        unsigned a0 = ldb2(Ah + kk),            a1 = ldb2(Ah + 8 * 128 + kk);
        unsigned a2 = ldb2(Ah + kk + 8),        a3 = ldb2(Ah + 8 * 128 + kk + 8);
        unsigned l0 = ldb2(Al + kk),            l1 = ldb2(Al + 8 * 128 + kk);
        unsigned l2 = ldb2(Al + kk + 8),        l3 = ldb2(Al + 8 * 128 + kk + 8);
#pragma unroll
        for (int nt = 0; nt < 8; nt++) {
            const __nv_bfloat16* Bh = g_oah + ((size_t)b * 1024 + hw0 + nt * 8 + gp) * 128 + q2 + kk;
            const __nv_bfloat16* Bl = g_oal + ((size_t)b * 1024 + hw0 + nt * 8 + gp) * 128 + q2 + kk;
            unsigned bh0 = ldb2(Bh), bh1 = ldb2(Bh + 8);
            unsigned bl0 = ldb2(Bl), bl1 = ldb2(Bl + 8);
            mma16816(acc[nt], a0, a1, a2, a3, bh0, bh1);
            mma16816(acc[nt], l0, l1, l2, l3, bh0, bh1);
            mma16816(acc[nt], a0, a1, a2, a3, bl0, bl1);
        }
    }
    int o = warp * 16 + gp;
    float bv0 = bias[o], bv1 = bias[o + 8];
    int e0 = ((o >> 1) << 2) + (o & 1);
#pragma unroll
    for (int nt = 0; nt < 8; nt++) {
        int hw = hw0 + nt * 8 + q2;
        int y = hw >> 5, x = hw & 31;
        size_t p0 = (((size_t)b * 34 + y + 1) * 34 + x + 1) * 256;
        split2i(acc[nt][0] + bv0, &g_o2[p0 + e0]);
        split2i(acc[nt][1] + bv0, &g_o2[p0 + 256 + e0]);
        split2i(acc[nt][2] + bv1, &g_o2[p0 + e0 + 16]);
        split2i(acc[nt][3] + bv1, &g_o2[p0 + 256 + e0 + 16]);
    }
}

// ---------------- 8) modulation -------------------------------------------------
__global__ void k_cmod(const float* __restrict__ emb, const float* __restrict__ mw,
                       const float* __restrict__ mb) {
    int t = threadIdx.x;
    if (t >= 56) return;
    int b = t / 14, j = t % 14;
    float acc = mb[j];
    for (int i = 0; i < 256; i++) {
        float v = emb[b * 256 + i];
        float sil = v / (1.f + __expf(-v));
        acc = fmaf(sil, mw[j * 256 + i], acc);
    }
    g_cmod[t] = acc;
}

// ---------------- 9/10) combine conv2 partials + per-batch stats ----------------
__global__ void k_upart() {
    int b = blockIdx.y, blk = blockIdx.x;
    size_t base = (size_t)b * 458752 + (size_t)blk * 14336;
    int tid = threadIdx.x;
    float s = 0.f, sq = 0.f;
    for (int i = tid; i < 14336; i += 256) {
        float v = g_u[base + i] + g_ub[base + i];
        g_u[base + i] = v;
        s += v; sq += v * v;
    }
#pragma unroll
    for (int off = 16; off; off >>= 1) {
        s  += __shfl_xor_sync(0xffffffffu, s,  off);
        sq += __shfl_xor_sync(0xffffffffu, sq, off);
    }
    __shared__ float rs[8], rq[8];
    int w = tid >> 5, lane = tid & 31;
    if (!lane) { rs[w] = s; rq[w] = sq; }
    __syncthreads();
    if (tid == 0) {
        float ts = 0.f, tq = 0.f;
#pragma unroll
        for (int i = 0; i < 8; i++) { ts += rs[i]; tq += rq[i]; }
        g_psum[b * 32 + blk] = ts;
        g_psq [b * 32 + blk] = tq;
    }
}
__global__ void k_ucomb() {
    int b = threadIdx.x;
    if (b < 4) {
        float s = 0.f, sq = 0.f;
        for (int i = 0; i < 32; i++) { s += g_psum[b * 32 + i]; sq += g_psq[b * 32 + i]; }
        float mean = s / 458752.f;
        float var  = sq / 458752.f - mean * mean;
        g_stats[b * 2]     = mean;
        g_stats[b * 2 + 1] = rsqrtf(var + EPSV);
    }
}

// ---------------- 11) final fused elementwise -----------------------------------
__global__ void k_final(const float* __restrict__ ew, const float* __restrict__ eb,
                        const float* __restrict__ fw, const float* __restrict__ fb,
                        float* __restrict__ out) {
    int b = blockIdx.y;
    int p = blockIdx.x * 256 + threadIdx.x;
    __shared__ float s_ew[98], s_eb[14], s_fw[49], s_fb[7], s_sc[7], s_sh[7];
    __shared__ float s_mean, s_istd;
    int t = threadIdx.x;
    if (t < 98) s_ew[t] = ew[t];
    if (t < 49) s_fw[t] = fw[t];
    if (t < 14) s_eb[t] = eb[t];
    if (t < 7)  { s_fb[t] = fb[t]; s_sc[t] = g_cmod[b * 14 + t]; s_sh[t] = g_cmod[b * 14 + 7 + t]; }
    if (t == 0) { s_mean = g_stats[b * 2]; s_istd = g_stats[b * 2 + 1]; }
    __syncthreads();

    float mean = s_mean, istd = s_istd;
    float uv[7], un[7];
#pragma unroll
    for (int e = 0; e < 7; e++) uv[e] = g_u[((size_t)b * 7 + e) * 65536 + p];
#pragma unroll
    for (int e = 0; e < 7; e++) un[e] = (uv[e] - mean) * istd * (1.f + s_sc[e]) + s_sh[e];

    float en[14];
#pragma unroll
    for (int j = 0; j < 14; j++) {
        float a = s_eb[j];
#pragma unroll
        for (int e = 0; e < 7; e++) a = fmaf(s_ew[j * 7 + e], un[e], a);
        en[j] = a;
    }
    float hf[7];
#pragma unroll
    for (int e = 0; e < 7; e++) hf[e] = geluf(un[e]) + en[e] * geluf(en[7 + e]);

#pragma unroll
    for (int o = 0; o < 7; o++) {
        float a = s_fb[o];
#pragma unroll
        for (int e = 0; e < 7; e++) a = fmaf(s_fw[o * 7 + e], hf[e], a);
        out[((size_t)b * 7 + o) * 65536 + p] = a + uv[o];
    }
}

// ---------------- launch --------------------------------------------------------
extern "C" void kernel_launch(void* const* d_in, const int* in_sizes, int n_in,
                              void* d_out, int out_size) {
    const float* x         = (const float*)d_in[0];
    const float* k_cond    = (const float*)d_in[1];
    const float* v_cond    = (const float*)d_in[2];
    const float* emb       = (const float*)d_in[3];
    const float* pos_embed = (const float*)d_in[4];
    const float* patch_w   = (const float*)d_in[5];
    const float* patch_b   = (const float*)d_in[6];
    const float* gn_gamma  = (const float*)d_in[7];
    const float* gn_beta   = (const float*)d_in[8];
    const float* fc1q_w    = (const float*)d_in[9];
    const float* fc1q_b    = (const float*)d_in[10];
    const float* fc2q_w    = (const float*)d_in[11];
    const float* fc2q_b    = (const float*)d_in[12];
    const float* outproj_w = (const float*)d_in[13];
    const float* outproj_b = (const float*)d_in[14];
    const float* unpatch_w = (const float*)d_in[15];
    const float* unpatch_b = (const float*)d_in[16];
    const float* mod_w     = (const float*)d_in[17];
    const float* mod_b     = (const float*)d_in[18];
    const float* enlarge_w = (const float*)d_in[19];
    const float* enlarge_b = (const float*)d_in[20];
    const float* ff2_w     = (const float*)d_in[21];
    const float* ff2_b     = (const float*)d_in[22];
    float* out = (float*)d_out;

    k_pack  <<<dim3(32, 12), 256>>>(x);
    k_packwc<448, 8, 28, 1><<<504, 256>>>(patch_w);
    k_packwq<<<384, 256>>>(fc1q_w, fc2q_w);
    k_convmma<448, 128, 4, 2, 8, 1><<<dim3(16, 2, 12), 128>>>(patch_b, pos_embed);
    k_gnorm<<<64, 256>>>(gn_gamma, gn_beta);
    k_qmma<<<dim3(32, 4), 256>>>(fc1q_b, fc2q_w, fc2q_b);
    k_packwo<<<64, 256>>>(outproj_w);
    k_attn<<<16384, 128>>>(k_cond, v_cond);
    k_omma<<<dim3(16, 4), 256>>>(outproj_b);
    k_packwc<128, 28, 8, 2><<<504, 256>>>(unpatch_w);
    k_convmma<128, 448, 7, 2, 8, 2><<<dim3(16, 4, 4), 224>>>(unpatch_b, (const float*)0);
    k_cmod<<<1, 64>>>(emb, mod_w, mod_b);
    k_upart<<<dim3(32, 4), 256>>>();
    k_ucomb<<<1, 32>>>();
    k_final<<<dim3(256, 4), 256>>>(enlarge_w, enlarge_b, ff2_w, ff2_b, out);
}

// round 8
// speedup vs baseline: 1.3517x; 1.1546x over previous
#include <cuda_runtime.h>
#include <cuda_bf16.h>
#include <math.h>

#define EPSV 1e-5f

// ---------------- scratch (__device__ globals; zero-init borders load-bearing) --
// conv inputs channel-last padded fp32 (tf32-pre-rounded), channels permuted
// within each 16-block as quads [c, c+4, c+8, c+12] (pos = (c&~15) + (c&3)*4 + ((c>>2)&3))
__device__ float g_xp[12*34*34*448];
__device__ float g_o2[4*34*34*128];
// fragment-packed tf32 conv weights: [tap][mtile][chunk][k8half][lane] uint4
__device__ uint4 g_w1p[9*8*28*64];
__device__ uint4 g_w2p[9*28*8*64];
__device__ __nv_bfloat16 g_wqh[256*384];
__device__ __nv_bfloat16 g_wql[256*384];
__device__ __nv_bfloat16 g_woh[128*128];
__device__ __nv_bfloat16 g_wol[128*128];
__device__ float         g_c1p[4][12*128*1024];  // conv1 K-split partials
__device__ __nv_bfloat16 g_xnh[12*128*1024];
__device__ __nv_bfloat16 g_xnl[12*128*1024];
__device__ float         g_q[4096*256];
__device__ __nv_bfloat16 g_oah[4*1024*128];      // attn out transposed [b][hw][C]
__device__ __nv_bfloat16 g_oal[4*1024*128];
__device__ float         g_u [4*7*65536];
__device__ float         g_ub[4*7*65536];        // conv2 K-split partial
__device__ float g_cmod[64];
__device__ float g_psum[128], g_psq[128], g_stats[8];

// ---------------- helpers ----------------
__device__ __forceinline__ void split2(float v, __nv_bfloat16* h, __nv_bfloat16* l) {
    __nv_bfloat16 hh = __float2bfloat16(v);
    *h = hh;
    *l = __float2bfloat16(v - __bfloat162float(hh));
}
__device__ __forceinline__ float geluf(float v) {
    return 0.5f * v * (1.0f + erff(v * 0.70710678118654752f));
}
__device__ __forceinline__ unsigned ldb2(const __nv_bfloat16* p) {
    return *reinterpret_cast<const unsigned*>(p);
}
__device__ __forceinline__ unsigned tf32r(float v) {
    unsigned r;
    asm("cvt.rna.tf32.f32 %0, %1;\n" : "=r"(r) : "f"(v));
    return r;
}
__device__ __forceinline__ int chpos(int c) {       // permuted in-16 position
    return (c & ~15) + ((c & 3) << 2) + ((c >> 2) & 3);
}
__device__ __forceinline__ void mma16816(float* c, unsigned a0, unsigned a1, unsigned a2, unsigned a3,
                                         unsigned b0, unsigned b1) {
    asm volatile("mma.sync.aligned.m16n8k16.row.col.f32.bf16.bf16.f32 "
        "{%0,%1,%2,%3}, {%4,%5,%6,%7}, {%8,%9}, {%0,%1,%2,%3};\n"
        : "+f"(c[0]), "+f"(c[1]), "+f"(c[2]), "+f"(c[3])
        : "r"(a0), "r"(a1), "r"(a2), "r"(a3), "r"(b0), "r"(b1));
}
__device__ __forceinline__ void mma_tf32(float* c, uint4 a, float b0, float b1) {
    asm volatile("mma.sync.aligned.m16n8k8.row.col.f32.tf32.tf32.f32 "
        "{%0,%1,%2,%3}, {%4,%5,%6,%7}, {%8,%9}, {%0,%1,%2,%3};\n"
        : "+f"(c[0]), "+f"(c[1]), "+f"(c[2]), "+f"(c[3])
        : "r"(a.x), "r"(a.y), "r"(a.z), "r"(a.w),
          "r"(__float_as_uint(b0)), "r"(__float_as_uint(b1)));
}
__device__ __forceinline__ void cpasync16(void* dst_smem, const void* src) {
    unsigned sa = (unsigned)__cvta_generic_to_shared(dst_smem);
    asm volatile("cp.async.cg.shared.global [%0], [%1], 16;\n" :: "r"(sa), "l"(src));
}

// ---------------- 1) pack x -> permuted channel-last padded tf32 ----------------
__global__ void k_pack(const float* __restrict__ x) {
    __shared__ float s[28 * 256];
    int y = blockIdx.x, nimg = blockIdx.y;   // nimg = b*3 + s
    int tid = threadIdx.x;
#pragma unroll
    for (int half = 0; half < 2; half++) {
        __syncthreads();
        for (int i = tid; i < 28 * 64; i += 256) {
            int row = i >> 6, col4 = i & 63;         // row = e*4 + pp
            int e = row >> 2, pp = row & 3;
            int p1 = half * 4 + pp;
            const float4* src = reinterpret_cast<const float4*>(
                x + (((size_t)nimg * 7 + e) * 256 + y * 8 + p1) * 256) + col4;
            reinterpret_cast<float4*>(s)[row * 64 + col4] = *src;
        }
        __syncthreads();
        for (int i = tid; i < 32 * 224; i += 256) {
            int xq = i / 224, cl = i % 224;
            int p1l = cl / 56, rem = cl % 56, p2 = rem / 7, e = rem % 7;
            float v = s[(e * 4 + p1l) * 256 + xq * 8 + p2];
            int c = half * 224 + cl;
            size_t d = (((size_t)nimg * 34 + y + 1) * 34 + xq + 1) * 448 + chpos(c);
            g_xp[d] = __uint_as_float(tf32r(v));
        }
    }
}

// ---------------- conv weight tf32 fragment packer ------------------------------
template<int CIN, int MTILES, int CHUNKS, int MODE>
__global__ void k_packwc(const float* __restrict__ w) {
    uint4* dst = (MODE == 1) ? g_w1p : g_w2p;
    int i = blockIdx.x * 256 + threadIdx.x;
    if (i >= 9 * MTILES * CHUNKS * 64) return;
    int lane = i & 31;
    int h    = (i >> 5) & 1;                 // k8 half
    int idx  = i >> 6;
    int chunk = idx % CHUNKS;
    int mtile = (idx / CHUNKS) % MTILES;
    int tap   = idx / (CHUNKS * MTILES);
    int m = mtile * 16 + (lane >> 2);
    int c = chunk * 16 + (lane & 3) + h * 8;
    uint4 r;
    r.x = tf32r(w[((size_t)m       * CIN + c    ) * 9 + tap]);
    r.y = tf32r(w[((size_t)(m + 8) * CIN + c    ) * 9 + tap]);
    r.z = tf32r(w[((size_t)m       * CIN + c + 4) * 9 + tap]);
    r.w = tf32r(w[((size_t)(m + 8) * CIN + c + 4) * 9 + tap]);
    dst[i] = r;
}

__global__ void k_packwq(const float* __restrict__ w1, const float* __restrict__ w2) {
    int i = blockIdx.x * 256 + threadIdx.x;               // weff[m=256][k=384], k=d*3+s
    if (i >= 256 * 384) return;
    int m = i / 384, k = i % 384;
    split2(w1[m * 128 + k / 3] * w2[k % 3], &g_wqh[i], &g_wql[i]);
}
__global__ void k_packwo(const float* __restrict__ w) {   // [o=128][c=128]
    int i = blockIdx.x * 256 + threadIdx.x;
    if (i >= 128 * 128) return;
    split2(w[i], &g_woh[i], &g_wol[i]);
}

// ---------------- 2/7) conv3x3 implicit GEMM, tf32 single-pass ------------------
// smem: [pix][16 floats], 16B segs XOR-swizzled by (pix&3) -> conflict-free LDS.128.
template<int CIN, int COUT, int WARPS, int MT, int NT, int KS, int MODE>
__global__ void __launch_bounds__(WARPS*32) k_convtf(const float* __restrict__ bias,
                                                     const float* __restrict__ pos) {
    const int THREADS = WARPS * 32;
    const int TOTCH = CIN / 16;
    const int KCH   = TOTCH / KS;
    const int MTILES = COUT / 16;
    const int PIX = (NT / 4 + 2) * 34;
    __shared__ __align__(16) float sbuf[2][PIX * 16];

    const float* inp = (MODE == 1) ? g_xp : g_o2;
    const uint4* wp = (MODE == 1) ? g_w1p : g_w2p;

    int kpart, mtb;
    if (MODE == 1) { kpart = blockIdx.y; mtb = 0; }
    else           { kpart = blockIdx.y & 1; mtb = (blockIdx.y >> 1) * (WARPS * MT); }
    int y0  = blockIdx.x * (NT / 4);
    int img = blockIdx.z;
    int tid = threadIdx.x, lane = tid & 31, warp = tid >> 5;
    int gp = lane >> 2, q = lane & 3, q2 = q * 2;
    int ck0 = kpart * KCH;

    float acc[MT][NT][4];
#pragma unroll
    for (int a = 0; a < MT; a++)
#pragma unroll
        for (int b = 0; b < NT; b++)
#pragma unroll
            for (int c = 0; c < 4; c++) acc[a][b][c] = 0.f;

    size_t pixbase = ((size_t)img * 1156 + (size_t)y0 * 34) * CIN;

    auto stage = [&](int chunk, int buf) {
        for (int p = tid; p < PIX; p += THREADS) {
            const float* sg = inp + pixbase + (size_t)p * CIN + chunk * 16;
            float* db = &sbuf[buf][p * 16];
            int sw = p & 3;
#pragma unroll
            for (int s4 = 0; s4 < 4; s4++)
                cpasync16(db + ((s4 ^ sw) << 2), sg + s4 * 4);
        }
    };

    stage(ck0, 0);
    asm volatile("cp.async.commit_group;\n");

    for (int ck = 0; ck < KCH; ck++) {
        if (ck + 1 < KCH) {
            stage(ck0 + ck + 1, (ck + 1) & 1);
            asm volatile("cp.async.commit_group;\n");
            asm volatile("cp.async.wait_group 1;\n");
        } else {
            asm volatile("cp.async.wait_group 0;\n");
        }
        __syncthreads();
        const float* sb = sbuf[ck & 1];
        int chunk = ck0 + ck;
#pragma unroll
        for (int tap = 0; tap < 9; tap++) {
            const int ky = tap / 3, kx = tap % 3;
            uint4 A0[MT], A1[MT];
#pragma unroll
            for (int mt = 0; mt < MT; mt++) {
                const uint4* pa = wp + ((((size_t)tap * MTILES + mtb + warp * MT + mt) * TOTCH + chunk) << 6) + lane;
                A0[mt] = pa[0];
                A1[mt] = pa[32];
            }
#pragma unroll
            for (int nt = 0; nt < NT; nt++) {
                int n  = nt * 8 + gp;
                int rc = (ky + (n >> 5)) * 34 + (n & 31) + kx;
                float4 f = *reinterpret_cast<const float4*>(&sb[rc * 16 + ((q ^ (rc & 3)) << 2)]);
#pragma unroll
                for (int mt = 0; mt < MT; mt++) {
                    mma_tf32(acc[mt][nt], A0[mt], f.x, f.y);
                    mma_tf32(acc[mt][nt], A1[mt], f.z, f.w);
                }
            }
        }
        __syncthreads();
    }

#pragma unroll
    for (int mt = 0; mt < MT; mt++) {
        int m = (mtb + warp * MT + mt) * 16 + gp;
        float bv0 = (kpart == 0) ? bias[m] : 0.f;
        float bv1 = (kpart == 0) ? bias[m + 8] : 0.f;
#pragma unroll
        for (int nt = 0; nt < NT; nt++) {
            int n  = nt * 8 + q2;
            int yo = y0 + (n >> 5);
            int x  = n & 31;
            float v0 = acc[mt][nt][0] + bv0;
            float v1 = acc[mt][nt][1] + bv0;
            float v2 = acc[mt][nt][2] + bv1;
            float v3 = acc[mt][nt][3] + bv1;
            if (MODE == 1) {
                float* dst = g_c1p[kpart];
                if (kpart == 0) {
                    v0 += pos[m * 1024 + yo * 32 + x];
                    v1 += pos[m * 1024 + yo * 32 + x + 1];
                    v2 += pos[(m + 8) * 1024 + yo * 32 + x];
                    v3 += pos[(m + 8) * 1024 + yo * 32 + x + 1];
                }
                *reinterpret_cast<float2*>(&dst[((img * 128 + m) * 32 + yo) * 32 + x])     = make_float2(v0, v1);
                *reinterpret_cast<float2*>(&dst[((img * 128 + m + 8) * 32 + yo) * 32 + x]) = make_float2(v2, v3);
            } else {
                float* dst = (kpart == 0) ? g_u : g_ub;
                int o = m;
                int p1i = o / 56, rem = o % 56, p2i = rem / 7, e = rem % 7;
                size_t base = (((size_t)img * 7 + e) * 256 + yo * 8 + p1i) * 256;
                dst[base + x * 8 + p2i]       = v0;
                dst[base + (x + 1) * 8 + p2i] = v1;
                o = m + 8;
                p1i = o / 56; rem = o % 56; p2i = rem / 7; e = rem % 7;
                base = (((size_t)img * 7 + e) * 256 + yo * 8 + p1i) * 256;
                dst[base + x * 8 + p2i]       = v2;
                dst[base + (x + 1) * 8 + p2i] = v3;
            }
        }
    }
}

// ---------------- 3) group norm (sums 4 K-split partials) -> bf16 hi/lo ---------
__global__ void k_gnorm(const float* __restrict__ gamma, const float* __restrict__ beta) {
    int b = blockIdx.x >> 4, g = blockIdx.x & 15;
    const int CH = 24576;
    size_t base = (size_t)b * 393216 + (size_t)g * CH;
    int tid = threadIdx.x;
    float s = 0.f, sq = 0.f;
    for (int i = tid; i < CH; i += 256) {
        float v = g_c1p[0][base + i] + g_c1p[1][base + i] + g_c1p[2][base + i] + g_c1p[3][base + i];
        s += v; sq += v * v;
    }
#pragma unroll
    for (int off = 16; off; off >>= 1) {
        s  += __shfl_xor_sync(0xffffffffu, s,  off);
        sq += __shfl_xor_sync(0xffffffffu, sq, off);
    }
    __shared__ float rs[8], rq[8];
    int w = tid >> 5, lane = tid & 31;
    if (!lane) { rs[w] = s; rq[w] = sq; }
    __syncthreads();
    s = 0.f; sq = 0.f;
#pragma unroll
    for (int i = 0; i < 8; i++) { s += rs[i]; sq += rq[i]; }
    float mean = s / (float)CH;
    float var  = sq / (float)CH - mean * mean;
    float inv  = rsqrtf(var + EPSV);
    for (int i = tid; i < CH; i += 256) {
        int dch = g * 8 + i / 3072;
        float v0 = g_c1p[0][base + i] + g_c1p[1][base + i] + g_c1p[2][base + i] + g_c1p[3][base + i];
        float v = (v0 - mean) * inv * gamma[dch] + beta[dch];
        split2(v, &g_xnh[base + i], &g_xnl[base + i]);
    }
}

// ---------------- 4) q GEMM via mma: C[4096][256] = xn[4096][384] @ weff^T ------
__global__ void __launch_bounds__(256) k_qmma(const float* __restrict__ b1,
                                              const float* __restrict__ w2,
                                              const float* __restrict__ b2) {
    int n0 = blockIdx.x * 128, o0 = blockIdx.y * 64;
    int tid = threadIdx.x, lane = tid & 31, warp = tid >> 5;
    int q2 = (lane & 3) * 2, gp = lane >> 2;
    float acc[8][4];
#pragma unroll
    for (int a = 0; a < 8; a++)
#pragma unroll
        for (int c = 0; c < 4; c++) acc[a][c] = 0.f;

    const __nv_bfloat16* Ah = g_xnh + (size_t)(n0 + warp * 16 + gp) * 384 + q2;
    const __nv_bfloat16* Al = g_xnl + (size_t)(n0 + warp * 16 + gp) * 384 + q2;

    for (int kk = 0; kk < 384; kk += 16) {
        unsigned a0 = ldb2(Ah + kk),            a1 = ldb2(Ah + 8 * 384 + kk);
        unsigned a2 = ldb2(Ah + kk + 8),        a3 = ldb2(Ah + 8 * 384 + kk + 8);
        unsigned l0 = ldb2(Al + kk),            l1 = ldb2(Al + 8 * 384 + kk);
        unsigned l2 = ldb2(Al + kk + 8),        l3 = ldb2(Al + 8 * 384 + kk + 8);
#pragma unroll
        for (int nt = 0; nt < 8; nt++) {
            const __nv_bfloat16* Bh = g_wqh + (size_t)(o0 + nt * 8 + gp) * 384 + q2 + kk;
            const __nv_bfloat16* Bl = g_wql + (size_t)(o0 + nt * 8 + gp) * 384 + q2 + kk;
            unsigned bh0 = ldb2(Bh), bh1 = ldb2(Bh + 8);
            unsigned bl0 = ldb2(Bl), bl1 = ldb2(Bl + 8);
            mma16816(acc[nt], a0, a1, a2, a3, bh0, bh1);
            mma16816(acc[nt], l0, l1, l2, l3, bh0, bh1);
            mma16816(acc[nt], a0, a1, a2, a3, bl0, bl1);
        }
    }
    float sws = w2[0] + w2[1] + w2[2];
    float fb = b2[0];
    int n = n0 + warp * 16 + gp;
#pragma unroll
    for (int nt = 0; nt < 8; nt++) {
        int o = o0 + nt * 8 + q2;
        g_q[n * 256 + o]           = acc[nt][0] + b1[o] * sws + fb;
        g_q[n * 256 + o + 1]       = acc[nt][1] + b1[o + 1] * sws + fb;
        g_q[(n + 8) * 256 + o]     = acc[nt][2] + b1[o] * sws + fb;
        g_q[(n + 8) * 256 + o + 1] = acc[nt][3] + b1[o + 1] * sws + fb;
    }
}

// ---------------- 5) attention (one block per row r) ----------------------------
__global__ void k_attn(const float* __restrict__ kc, const float* __restrict__ vc) {
    int r = blockIdx.x;
    int tid = threadIdx.x;     // 128
    int w = tid >> 5, lane = tid & 31;
    __shared__ float sq[64];
    __shared__ float se[128];
    __shared__ float red[4], red2[4];
    __shared__ float oacc[4][32];

    if (tid < 64) sq[tid] = g_q[r * 64 + tid];
    __syncthreads();

    const float4* krow = (const float4*)(kc + (size_t)r * 8192 + (size_t)tid * 64);
    float dot = 0.f;
#pragma unroll
    for (int i = 0; i < 16; i++) {
        float4 kv = krow[i];
        dot += kv.x * sq[i * 4] + kv.y * sq[i * 4 + 1] + kv.z * sq[i * 4 + 2] + kv.w * sq[i * 4 + 3];
    }
    dot *= 0.125f;

    float m = dot;
#pragma unroll
    for (int off = 16; off; off >>= 1) m = fmaxf(m, __shfl_xor_sync(0xffffffffu, m, off));
    if (!lane) red[w] = m;
    __syncthreads();
    m = fmaxf(fmaxf(red[0], red[1]), fmaxf(red[2], red[3]));

    float e = __expf(dot - m);
    se[tid] = e;
    float s = e;
#pragma unroll
    for (int off = 16; off; off >>= 1) s += __shfl_xor_sync(0xffffffffu, s, off);
    if (!lane) red2[w] = s;
    __syncthreads();
    float inv = 1.f / (red2[0] + red2[1] + red2[2] + red2[3]);

    const float* vbase = vc + (size_t)r * 4096;
    float a = 0.f;
#pragma unroll 4
    for (int li = 0; li < 32; li++) {
        int l = w * 32 + li;
        a = fmaf(se[l], vbase[l * 32 + lane], a);
    }
    oacc[w][lane] = a;
    __syncthreads();
    if (tid < 32) {
        float tot = (oacc[0][tid] + oacc[1][tid] + oacc[2][tid] + oacc[3][tid]) * inv;
        int lin = (r & 4095) * 128 + (r >> 12) * 32 + tid;   // (Nq,DC) flat index
        int bb = lin >> 17;
        int C  = (lin >> 10) & 127;
        int hw = lin & 1023;
        size_t d = ((size_t)(bb * 1024 + hw)) * 128 + C;     // transposed [b][hw][C]
        split2(tot, &g_oah[d], &g_oal[d]);
    }
}

// ---------------- 6) out projection via mma -> permuted tf32 conv2 input --------
__global__ void __launch_bounds__(256) k_omma(const float* __restrict__ bias) {
    int hw0 = blockIdx.x * 64, b = blockIdx.y;
    int tid = threadIdx.x, lane = tid & 31, warp = tid >> 5;
    int q2 = (lane & 3) * 2, gp = lane >> 2;
    float acc[8][4];
#pragma unroll
    for (int a = 0; a < 8; a++)
#pragma unroll
        for (int c = 0; c < 4; c++) acc[a][c] = 0.f;

    const __nv_bfloat16* Ah = g_woh + (size_t)(warp * 16 + gp) * 128 + q2;
    const __nv_bfloat16* Al = g_wol + (size_t)(warp * 16 + gp) * 128 + q2;

    for (int kk = 0; kk < 128; kk += 16) {
        unsigned a0 = ldb2(Ah + kk),            a1 = ldb2(Ah + 8 * 128 + kk);
        unsigned a2 = ldb2(Ah + kk + 8),        a3 = ldb2(Ah + 8 * 128 + kk + 8);
        unsigned l0 = ldb2(Al + kk),            l1 = ldb2(Al + 8 * 128 + kk);
        unsigned l2 = ldb2(Al + kk + 8),        l3 = ldb2(Al + 8 * 128 + kk + 8);
#pragma unroll
        for (int nt = 0; nt < 8; nt++) {
            const __nv_bfloat16* Bh = g_oah + ((size_t)b * 1024 + hw0 + nt * 8 + gp) * 128 + q2 + kk;
            const __nv_bfloat16* Bl = g_oal + ((size_t)b * 1024 + hw0 + nt * 8 + gp) * 128 + q2 + kk;
            unsigned bh0 = ldb2(Bh), bh1 = ldb2(Bh + 8);
            unsigned bl0 = ldb2(Bl), bl1 = ldb2(Bl + 8);
            mma16816(acc[nt], a0, a1, a2, a3, bh0, bh1);
            mma16816(acc[nt], l0, l1, l2, l3, bh0, bh1);
            mma16816(acc[nt], a0, a1, a2, a3, bl0, bl1);
        }
    }
    int o = warp * 16 + gp;
    float bv0 = bias[o], bv1 = bias[o + 8];
    int cp0 = chpos(o), cp1 = chpos(o + 8);
#pragma unroll
    for (int nt = 0; nt < 8; nt++) {
        int hw = hw0 + nt * 8 + q2;
        int y = hw >> 5, x = hw & 31;
        size_t p0 = (((size_t)b * 34 + y + 1) * 34 + x + 1) * 128;
        g_o2[p0 + cp0]       = __uint_as_float(tf32r(acc[nt][0] + bv0));
        g_o2[p0 + 128 + cp0] = __uint_as_float(tf32r(acc[nt][1] + bv0));
        g_o2[p0 + cp1]       = __uint_as_float(tf32r(acc[nt][2] + bv1));
        g_o2[p0 + 128 + cp1] = __uint_as_float(tf32r(acc[nt][3] + bv1));
    }
}

// ---------------- 8) modulation -------------------------------------------------
__global__ void k_cmod(const float* __restrict__ emb, const float* __restrict__ mw,
                       const float* __restrict__ mb) {
    int t = threadIdx.x;
    if (t >= 56) return;
    int b = t / 14, j = t % 14;
    float acc = mb[j];
    for (int i = 0; i < 256; i++) {
        float v = emb[b * 256 + i];
        float sil = v / (1.f + __expf(-v));
        acc = fmaf(sil, mw[j * 256 + i], acc);
    }
    g_cmod[t] = acc;
}

// ---------------- 9/10) combine conv2 partials + per-batch stats ----------------
__global__ void k_upart() {
    int b = blockIdx.y, blk = blockIdx.x;
    size_t base = (size_t)b * 458752 + (size_t)blk * 14336;
    int tid = threadIdx.x;
    float s = 0.f, sq = 0.f;
    for (int i = tid; i < 14336; i += 256) {
        float v = g_u[base + i] + g_ub[base + i];
        g_u[base + i] = v;
        s += v; sq += v * v;
    }
#pragma unroll
    for (int off = 16; off; off >>= 1) {
        s  += __shfl_xor_sync(0xffffffffu, s,  off);
        sq += __shfl_xor_sync(0xffffffffu, sq, off);
    }
    __shared__ float rs[8], rq[8];
    int w = tid >> 5, lane = tid & 31;
    if (!lane) { rs[w] = s; rq[w] = sq; }
    __syncthreads();
    if (tid == 0) {
        float ts = 0.f, tq = 0.f;
#pragma unroll
        for (int i = 0; i < 8; i++) { ts += rs[i]; tq += rq[i]; }
        g_psum[b * 32 + blk] = ts;
        g_psq [b * 32 + blk] = tq;
    }
}
__global__ void k_ucomb() {
    int b = threadIdx.x;
    if (b < 4) {
        float s = 0.f, sq = 0.f;
        for (int i = 0; i < 32; i++) { s += g_psum[b * 32 + i]; sq += g_psq[b * 32 + i]; }
        float mean = s / 458752.f;
        float var  = sq / 458752.f - mean * mean;
        g_stats[b * 2]     = mean;
        g_stats[b * 2 + 1] = rsqrtf(var + EPSV);
    }
}

// ---------------- 11) final fused elementwise -----------------------------------
__global__ void k_final(const float* __restrict__ ew, const float* __restrict__ eb,
                        const float* __restrict__ fw, const float* __restrict__ fb,
                        float* __restrict__ out) {
    int b = blockIdx.y;
    int p = blockIdx.x * 256 + threadIdx.x;
    __shared__ float s_ew[98], s_eb[14], s_fw[49], s_fb[7], s_sc[7], s_sh[7];
    __shared__ float s_mean, s_istd;
    int t = threadIdx.x;
    if (t < 98) s_ew[t] = ew[t];
    if (t < 49) s_fw[t] = fw[t];
    if (t < 14) s_eb[t] = eb[t];
    if (t < 7)  { s_fb[t] = fb[t]; s_sc[t] = g_cmod[b * 14 + t]; s_sh[t] = g_cmod[b * 14 + 7 + t]; }
    if (t == 0) { s_mean = g_stats[b * 2]; s_istd = g_stats[b * 2 + 1]; }
    __syncthreads();

    float mean = s_mean, istd = s_istd;
    float uv[7], un[7];
#pragma unroll
    for (int e = 0; e < 7; e++) uv[e] = g_u[((size_t)b * 7 + e) * 65536 + p];
#pragma unroll
    for (int e = 0; e < 7; e++) un[e] = (uv[e] - mean) * istd * (1.f + s_sc[e]) + s_sh[e];

    float en[14];
#pragma unroll
    for (int j = 0; j < 14; j++) {
        float a = s_eb[j];
#pragma unroll
        for (int e = 0; e < 7; e++) a = fmaf(s_ew[j * 7 + e], un[e], a);
        en[j] = a;
    }
    float hf[7];
#pragma unroll
    for (int e = 0; e < 7; e++) hf[e] = geluf(un[e]) + en[e] * geluf(en[7 + e]);

#pragma unroll
    for (int o = 0; o < 7; o++) {
        float a = s_fb[o];
#pragma unroll
        for (int e = 0; e < 7; e++) a = fmaf(s_fw[o * 7 + e], hf[e], a);
        out[((size_t)b * 7 + o) * 65536 + p] = a + uv[o];
    }
}

// ---------------- launch --------------------------------------------------------
extern "C" void kernel_launch(void* const* d_in, const int* in_sizes, int n_in,
                              void* d_out, int out_size) {
    const float* x         = (const float*)d_in[0];
    const float* k_cond    = (const float*)d_in[1];
    const float* v_cond    = (const float*)d_in[2];
    const float* emb       = (const float*)d_in[3];
    const float* pos_embed = (const float*)d_in[4];
    const float* patch_w   = (const float*)d_in[5];
    const float* patch_b   = (const float*)d_in[6];
    const float* gn_gamma  = (const float*)d_in[7];
    const float* gn_beta   = (const float*)d_in[8];
    const float* fc1q_w    = (const float*)d_in[9];
    const float* fc1q_b    = (const float*)d_in[10];
    const float* fc2q_w    = (const float*)d_in[11];
    const float* fc2q_b    = (const float*)d_in[12];
    const float* outproj_w = (const float*)d_in[13];
    const float* outproj_b = (const float*)d_in[14];
    const float* unpatch_w = (const float*)d_in[15];
    const float* unpatch_b = (const float*)d_in[16];
    const float* mod_w     = (const float*)d_in[17];
    const float* mod_b     = (const float*)d_in[18];
    const float* enlarge_w = (const float*)d_in[19];
    const float* enlarge_b = (const float*)d_in[20];
    const float* ff2_w     = (const float*)d_in[21];
    const float* ff2_b     = (const float*)d_in[22];
    float* out = (float*)d_out;

    k_pack  <<<dim3(32, 12), 256>>>(x);
    k_packwc<448, 8, 28, 1><<<504, 256>>>(patch_w);
    k_packwq<<<384, 256>>>(fc1q_w, fc2q_w);
    k_convtf<448, 128, 4, 2, 8, 4, 1><<<dim3(16, 4, 12), 128>>>(patch_b, pos_embed);
    k_gnorm<<<64, 256>>>(gn_gamma, gn_beta);
    k_qmma<<<dim3(32, 4), 256>>>(fc1q_b, fc2q_w, fc2q_b);
    k_packwo<<<64, 256>>>(outproj_w);
    k_attn<<<16384, 128>>>(k_cond, v_cond);
    k_omma<<<dim3(16, 4), 256>>>(outproj_b);
    k_packwc<128, 28, 8, 2><<<504, 256>>>(unpatch_w);
    k_convtf<128, 448, 7, 2, 4, 2, 2><<<dim3(32, 4, 4), 224>>>(unpatch_b, (const float*)0);
    k_cmod<<<1, 64>>>(emb, mod_w, mod_b);
    k_upart<<<dim3(32, 4), 256>>>();
    k_ucomb<<<1, 32>>>();
    k_final<<<dim3(256, 4), 256>>>(enlarge_w, enlarge_b, ff2_w, ff2_b, out);
}